// round 1
// baseline (speedup 1.0000x reference)
#include <cuda_runtime.h>

// GlobalFilter: y = irfft2(rfft2(x, ortho) * W, ortho), x: [128,14,14,768] f32,
// W: [14,8,768,2] f32. Fused 4-pass small-DFT pipeline, all twiddles are
// compile-time immediates (N=14).

#define BB 128
#define HH 14
#define WW 14
#define CC 768
#define CB 128          // channels per CTA
#define NTHREADS 256    // 2 threads per channel (role 0 / role 1)
#define CHSTRIDE 393    // 14*28 + 1 pad -> conflict-free (gcd(393%32=9,32)=1)

__global__ __launch_bounds__(NTHREADS, 1)
void gfilter_kernel(const float* __restrict__ x,
                    const float* __restrict__ wt,
                    float* __restrict__ y)
{
    // cos/sin(2*pi*m/14), m = 0..13
    constexpr float COS14[14] = {
         1.0f,                 0.9009688679024191f,  0.6234898018587336f,
         0.22252093395631445f,-0.22252093395631445f,-0.6234898018587336f,
        -0.9009688679024191f, -1.0f,                -0.9009688679024191f,
        -0.6234898018587336f, -0.22252093395631445f, 0.22252093395631445f,
         0.6234898018587336f,  0.9009688679024191f
    };
    constexpr float SIN14[14] = {
         0.0f,                 0.43388373911755823f, 0.7818314824680298f,
         0.9749279121818236f,  0.9749279121818236f,  0.7818314824680298f,
         0.43388373911755823f, 0.0f,                -0.43388373911755823f,
        -0.7818314824680298f, -0.9749279121818236f, -0.9749279121818236f,
        -0.7818314824680298f, -0.43388373911755823f
    };

    extern __shared__ float sbuf[];

    const int tid  = threadIdx.x;
    const int cl   = tid & (CB - 1);   // local channel
    const int role = tid >> 7;         // 0 or 1
    const int b    = blockIdx.y;
    const int c    = blockIdx.x * CB + cl;

    float* buf = sbuf + cl * CHSTRIDE; // per-channel scratch: [14 rows][28 floats]

    const float* xb = x + ((size_t)b * (HH * WW)) * CC + c;

    // ---------------- Pass 1: DFT over H -> G[kh=0..7][w], complex ----------
    // G[kh,w] = sum_h x[h,w] * e^{-2pi i kh h / 14}
    #pragma unroll
    for (int wi = 0; wi < 7; ++wi) {
        const int w0 = role * 7 + wi;
        float xv[14];
        #pragma unroll
        for (int h = 0; h < 14; ++h)
            xv[h] = xb[(size_t)(h * 14 + w0) * CC];
        #pragma unroll
        for (int kh = 0; kh < 8; ++kh) {
            float gr = 0.f, gi = 0.f;
            #pragma unroll
            for (int h = 0; h < 14; ++h) {
                const int m = (kh * h) % 14;
                gr = fmaf(xv[h],  COS14[m], gr);
                gi = fmaf(xv[h], -SIN14[m], gi);
            }
            buf[kh * 28 + 2 * w0]     = gr;
            buf[kh * 28 + 2 * w0 + 1] = gi;
        }
    }
    __syncthreads();

    // ---------------- Pass 2: DFT over W + weight multiply ------------------
    // Xf[kh,kw]     = sum_w G[kh,w] e^{-2pi i kw w/14}        (kh = 0..7)
    // Xf[14-kh,kw]  = conj( sum_w G[kh,w] e^{+2pi i kw w/14} ) (kh = 1..6)
    // Z = Xf * weight, stored at buf[kh'][2*kw (+1)]
    const float2* wt2 = reinterpret_cast<const float2*>(wt);
    #pragma unroll
    for (int ki = 0; ki < 4; ++ki) {
        const int kh = role * 4 + ki;
        float gr[14], gi[14];
        #pragma unroll
        for (int w0 = 0; w0 < 14; ++w0) {
            gr[w0] = buf[kh * 28 + 2 * w0];
            gi[w0] = buf[kh * 28 + 2 * w0 + 1];
        }
        #pragma unroll
        for (int kw = 0; kw < 8; ++kw) {
            float Pr = 0.f, Pi = 0.f, Qr = 0.f, Qi = 0.f;
            #pragma unroll
            for (int w0 = 0; w0 < 14; ++w0) {
                const int m = (kw * w0) % 14;
                const float cc = COS14[m], ss = SIN14[m];
                Pr = fmaf(gr[w0], cc, Pr); Pr = fmaf(gi[w0],  ss, Pr);
                Pi = fmaf(gi[w0], cc, Pi); Pi = fmaf(-gr[w0], ss, Pi);
                Qr = fmaf(gr[w0], cc, Qr); Qr = fmaf(-gi[w0], ss, Qr);
                Qi = fmaf(gi[w0], cc, Qi); Qi = fmaf(gr[w0],  ss, Qi);
            }
            const float2 w0v = wt2[(size_t)(kh * 8 + kw) * CC + c];
            // Z[kh,kw] = P * (wr + i wi)
            buf[kh * 28 + 2 * kw]     = Pr * w0v.x - Pi * w0v.y;
            buf[kh * 28 + 2 * kw + 1] = Pr * w0v.y + Pi * w0v.x;
            if (kh >= 1 && kh <= 6) {
                const int kh2 = 14 - kh;
                const float2 w1v = wt2[(size_t)(kh2 * 8 + kw) * CC + c];
                // Z[kh2,kw] = conj(Q) * (wr + i wi) = (Qr - iQi)(wr + i wi)
                buf[kh2 * 28 + 2 * kw]     = Qr * w1v.x + Qi * w1v.y;
                buf[kh2 * 28 + 2 * kw + 1] = Qr * w1v.y - Qi * w1v.x;
            }
        }
    }
    __syncthreads();

    // ---------------- Pass 3: inverse DFT over H -----------------------------
    // Y1[h,kw] = sum_{kh=0..13} Z[kh,kw] e^{+2pi i kh h/14}, in-place by column
    #pragma unroll
    for (int ki = 0; ki < 4; ++ki) {
        const int kw = role * 4 + ki;
        float zr[14], zi[14];
        #pragma unroll
        for (int r = 0; r < 14; ++r) {
            zr[r] = buf[r * 28 + 2 * kw];
            zi[r] = buf[r * 28 + 2 * kw + 1];
        }
        #pragma unroll
        for (int h = 0; h < 14; ++h) {
            float yr = 0.f, yi = 0.f;
            #pragma unroll
            for (int r = 0; r < 14; ++r) {
                const int m = (r * h) % 14;
                const float cc = COS14[m], ss = SIN14[m];
                yr = fmaf(zr[r], cc, yr); yr = fmaf(-zi[r], ss, yr);
                yi = fmaf(zi[r], cc, yi); yi = fmaf(zr[r],  ss, yi);
            }
            buf[h * 28 + 2 * kw]     = yr;
            buf[h * 28 + 2 * kw + 1] = yi;
        }
    }
    __syncthreads();

    // ---------------- Pass 4: c2r over W + ortho scale, write out ------------
    // y[h,w] = (1/196) [ Re Y1[h,0] + (-1)^w Re Y1[h,7]
    //                    + 2 sum_{kw=1..6} (Yr cos - Yi sin) ]
    float* yb = y + ((size_t)b * (HH * WW)) * CC + c;
    #pragma unroll
    for (int hi = 0; hi < 7; ++hi) {
        const int h = role * 7 + hi;
        float yr[8], yi[8];
        #pragma unroll
        for (int kw = 0; kw < 8; ++kw) {
            yr[kw] = buf[h * 28 + 2 * kw];
            yi[kw] = buf[h * 28 + 2 * kw + 1];
        }
        #pragma unroll
        for (int w0 = 0; w0 < 14; ++w0) {
            float acc = 0.5f * yr[0] + ((w0 & 1) ? -0.5f : 0.5f) * yr[7];
            #pragma unroll
            for (int kw = 1; kw < 7; ++kw) {
                const int m = (kw * w0) % 14;
                acc = fmaf(yr[kw],  COS14[m], acc);
                acc = fmaf(-yi[kw], SIN14[m], acc);
            }
            yb[(size_t)(h * 14 + w0) * CC] = acc * (1.0f / 98.0f);
        }
    }
}

extern "C" void kernel_launch(void* const* d_in, const int* in_sizes, int n_in,
                              void* d_out, int out_size)
{
    (void)in_sizes; (void)n_in; (void)out_size;
    const float* x  = (const float*)d_in[0];
    const float* wt = (const float*)d_in[1];
    float* y        = (float*)d_out;

    const int smem_bytes = CHSTRIDE * CB * (int)sizeof(float); // 201216
    cudaFuncSetAttribute(gfilter_kernel,
                         cudaFuncAttributeMaxDynamicSharedMemorySize, smem_bytes);

    dim3 grid(CC / CB, BB); // (6, 128)
    gfilter_kernel<<<grid, NTHREADS, smem_bytes>>>(x, wt, y);
}

// round 2
// speedup vs baseline: 2.5484x; 2.5484x over previous
#include <cuda_runtime.h>

// GlobalFilter: y = irfft2(rfft2(x, ortho) * W, ortho)
// x: [128,14,14,768] f32, W: [14,8,768,2] f32.
// Fused 4-pass small-DFT pipeline, compile-time twiddles (N=14).
// R2: 4 threads/channel, compact smem (229 f32/ch), 3 CTAs/SM target.

#define CC  768
#define CB  64          // channels per CTA
#define NTH 256         // 4 threads per channel
#define STR 229         // smem floats per channel (odd -> conflict-free)

#define DEF_TWIDDLES \
    constexpr float COS14[14] = { \
         1.0f,                 0.9009688679024191f,  0.6234898018587336f, \
         0.22252093395631445f,-0.22252093395631445f,-0.6234898018587336f, \
        -0.9009688679024191f, -1.0f,                -0.9009688679024191f, \
        -0.6234898018587336f, -0.22252093395631445f, 0.22252093395631445f, \
         0.6234898018587336f,  0.9009688679024191f }; \
    constexpr float SIN14[14] = { \
         0.0f,                 0.43388373911755823f, 0.7818314824680298f, \
         0.9749279121818236f,  0.9749279121818236f,  0.7818314824680298f, \
         0.43388373911755823f, 0.0f,                -0.43388373911755823f, \
        -0.7818314824680298f, -0.9749279121818236f, -0.9749279121818236f, \
        -0.7818314824680298f, -0.43388373911755823f }

// DFT over W of one kh-row of G + complex weight multiply; writes Z rows
// (own row kh and Hermitian mirror 14-kh) at compact stride-16 layout.
__device__ __forceinline__ void pass2_row(int kh,
                                          const float* __restrict__ gr,
                                          const float* __restrict__ gi,
                                          float* __restrict__ buf,
                                          const float2* __restrict__ wt2c)
{
    DEF_TWIDDLES;
    #pragma unroll
    for (int kw = 0; kw < 8; ++kw) {
        float Pr = 0.f, Pi = 0.f, Qr = 0.f, Qi = 0.f;
        #pragma unroll
        for (int w = 0; w < 14; ++w) {
            const int m = (kw * w) % 14;
            const float cc = COS14[m], ss = SIN14[m];
            Pr = fmaf(gr[w], cc, Pr); Pr = fmaf(gi[w],  ss, Pr);
            Pi = fmaf(gi[w], cc, Pi); Pi = fmaf(-gr[w], ss, Pi);
            Qr = fmaf(gr[w], cc, Qr); Qr = fmaf(-gi[w], ss, Qr);
            Qi = fmaf(gi[w], cc, Qi); Qi = fmaf(gr[w],  ss, Qi);
        }
        const float2 w0v = wt2c[(kh * 8 + kw) * CC];
        buf[kh * 16 + 2 * kw]     = Pr * w0v.x - Pi * w0v.y;
        buf[kh * 16 + 2 * kw + 1] = Pr * w0v.y + Pi * w0v.x;
        if (kh >= 1 && kh <= 6) {
            const int kh2 = 14 - kh;
            const float2 w1v = wt2c[(kh2 * 8 + kw) * CC];
            buf[kh2 * 16 + 2 * kw]     = Qr * w1v.x + Qi * w1v.y;
            buf[kh2 * 16 + 2 * kw + 1] = Qr * w1v.y - Qi * w1v.x;
        }
    }
}

__global__ __launch_bounds__(NTH, 3)
void gfilter_kernel(const float* __restrict__ x,
                    const float* __restrict__ wt,
                    float* __restrict__ y)
{
    DEF_TWIDDLES;
    extern __shared__ float sbuf[];

    const int tid  = threadIdx.x;
    const int cl   = tid & (CB - 1);
    const int role = tid >> 6;            // 0..3, uniform per warp
    const int b    = blockIdx.y;
    const int c    = blockIdx.x * CB + cl;

    float* buf = sbuf + cl * STR;
    const int base = (b * 196) * CC + c;  // fits in int32
    const float* xb = x + base;

    // ---- Pass 1: real DFT over H -> G[kh=0..7][w] complex (stride-28 rows) --
    #pragma unroll
    for (int i = 0; i < 4; ++i) {
        const int w0 = role + 4 * i;
        if (w0 < 14) {
            float xv[14];
            #pragma unroll
            for (int h = 0; h < 14; ++h)
                xv[h] = xb[(h * 14 + w0) * CC];
            #pragma unroll
            for (int kh = 0; kh < 8; ++kh) {
                float gr = 0.f, gi = 0.f;
                #pragma unroll
                for (int h = 0; h < 14; ++h) {
                    const int m = (kh * h) % 14;
                    gr = fmaf(xv[h],  COS14[m], gr);
                    gi = fmaf(xv[h], -SIN14[m], gi);
                }
                buf[kh * 28 + 2 * w0]     = gr;
                buf[kh * 28 + 2 * w0 + 1] = gi;
            }
        }
    }
    __syncthreads();

    // ---- Pass 2: DFT over W + weight multiply -> Z (stride-16 rows) --------
    // In-place overwrite of G region: stage reads in regs, sync, then write.
    {
        const int kh0 = 2 * role, kh1 = kh0 + 1;
        float g0r[14], g0i[14], g1r[14], g1i[14];
        #pragma unroll
        for (int w = 0; w < 14; ++w) {
            g0r[w] = buf[kh0 * 28 + 2 * w];
            g0i[w] = buf[kh0 * 28 + 2 * w + 1];
            g1r[w] = buf[kh1 * 28 + 2 * w];
            g1i[w] = buf[kh1 * 28 + 2 * w + 1];
        }
        __syncthreads();
        const float2* wt2c = reinterpret_cast<const float2*>(wt) + c;
        pass2_row(kh0, g0r, g0i, buf, wt2c);
        pass2_row(kh1, g1r, g1i, buf, wt2c);
    }
    __syncthreads();

    // ---- Pass 3: inverse DFT over H (full 14), per-kw column, in place -----
    #pragma unroll
    for (int j = 0; j < 2; ++j) {
        const int kw = 2 * role + j;
        float zr[14], zi[14];
        #pragma unroll
        for (int r = 0; r < 14; ++r) {
            zr[r] = buf[r * 16 + 2 * kw];
            zi[r] = buf[r * 16 + 2 * kw + 1];
        }
        #pragma unroll
        for (int h = 0; h < 14; ++h) {
            float yr = 0.f, yi = 0.f;
            #pragma unroll
            for (int r = 0; r < 14; ++r) {
                const int m = (r * h) % 14;
                const float cc = COS14[m], ss = SIN14[m];
                yr = fmaf(zr[r], cc, yr); yr = fmaf(-zi[r], ss, yr);
                yi = fmaf(zi[r], cc, yi); yi = fmaf(zr[r],  ss, yi);
            }
            buf[h * 16 + 2 * kw]     = yr;
            buf[h * 16 + 2 * kw + 1] = yi;
        }
    }
    __syncthreads();

    // ---- Pass 4: c2r over W + ortho scale, write out ------------------------
    float* yb = y + base;
    #pragma unroll
    for (int i = 0; i < 4; ++i) {
        const int h = role + 4 * i;
        if (h < 14) {
            float yr[8], yi[8];
            #pragma unroll
            for (int kw = 0; kw < 8; ++kw) {
                yr[kw] = buf[h * 16 + 2 * kw];
                yi[kw] = buf[h * 16 + 2 * kw + 1];
            }
            #pragma unroll
            for (int w = 0; w < 14; ++w) {
                float acc = 0.5f * yr[0] + ((w & 1) ? -0.5f : 0.5f) * yr[7];
                #pragma unroll
                for (int kw = 1; kw < 7; ++kw) {
                    const int m = (kw * w) % 14;
                    acc = fmaf(yr[kw],  COS14[m], acc);
                    acc = fmaf(-yi[kw], SIN14[m], acc);
                }
                yb[(h * 14 + w) * CC] = acc * (1.0f / 98.0f);
            }
        }
    }
}

extern "C" void kernel_launch(void* const* d_in, const int* in_sizes, int n_in,
                              void* d_out, int out_size)
{
    (void)in_sizes; (void)n_in; (void)out_size;
    const float* x  = (const float*)d_in[0];
    const float* wt = (const float*)d_in[1];
    float* y        = (float*)d_out;

    const int smem_bytes = CB * STR * (int)sizeof(float); // 58624
    cudaFuncSetAttribute(gfilter_kernel,
                         cudaFuncAttributeMaxDynamicSharedMemorySize, smem_bytes);

    dim3 grid(CC / CB, 128); // (12, 128)
    gfilter_kernel<<<grid, NTH, smem_bytes>>>(x, wt, y);
}

// round 3
// speedup vs baseline: 3.8897x; 1.5263x over previous
#include <cuda_runtime.h>

// GlobalFilter: y = irfft2(rfft2(x, ortho) * W, ortho)
// x: [128,14,14,768] f32, W: [14,8,768,2] f32.
// R3: reflection-symmetry-folded DFTs in all 4 passes (~2.7x fewer FMAs).

#define CC  768
#define CB  64          // channels per CTA
#define NTH 256         // 4 threads per channel
#define STR 229         // smem floats per channel (odd stride -> conflict-free)

#define DEF_TWIDDLES \
    constexpr float COS14[14] = { \
         1.0f,                 0.9009688679024191f,  0.6234898018587336f, \
         0.22252093395631445f,-0.22252093395631445f,-0.6234898018587336f, \
        -0.9009688679024191f, -1.0f,                -0.9009688679024191f, \
        -0.6234898018587336f, -0.22252093395631445f, 0.22252093395631445f, \
         0.6234898018587336f,  0.9009688679024191f }; \
    constexpr float SIN14[14] = { \
         0.0f,                 0.43388373911755823f, 0.7818314824680298f, \
         0.9749279121818236f,  0.9749279121818236f,  0.7818314824680298f, \
         0.43388373911755823f, 0.0f,                -0.43388373911755823f, \
        -0.7818314824680298f, -0.9749279121818236f, -0.9749279121818236f, \
        -0.7818314824680298f, -0.43388373911755823f }

// Folded pass-2 row: G[kh][0..13] (as boundary + even/odd folds) -> Z rows
// kh and 14-kh (weight-multiplied), compact stride-16 layout.
__device__ __forceinline__ void pass2_row(int kh,
                                          float gr0, float gi0, float gr7, float gi7,
                                          const float* __restrict__ er,
                                          const float* __restrict__ orr,
                                          const float* __restrict__ ei,
                                          const float* __restrict__ oi,
                                          float* __restrict__ buf,
                                          const float2* __restrict__ wt2c)
{
    DEF_TWIDDLES;
    #pragma unroll
    for (int kw = 0; kw < 8; ++kw) {
        float A = 0.f, Bv = 0.f, Cv = 0.f, D = 0.f;
        #pragma unroll
        for (int j = 1; j <= 6; ++j) {
            const int m = (kw * j) % 14;
            A  = fmaf(er[j-1],  COS14[m], A);
            Bv = fmaf(oi[j-1],  SIN14[m], Bv);
            Cv = fmaf(ei[j-1],  COS14[m], Cv);
            D  = fmaf(orr[j-1], SIN14[m], D);
        }
        const float s = (kw & 1) ? -1.f : 1.f;
        const float baser = fmaf(s, gr7, gr0);
        const float basei = fmaf(s, gi7, gi0);
        const float Pr = baser + A + Bv;
        const float Pi = basei + Cv - D;
        const float2 w0v = wt2c[(kh * 8 + kw) * CC];
        buf[kh * 16 + 2 * kw]     = Pr * w0v.x - Pi * w0v.y;
        buf[kh * 16 + 2 * kw + 1] = Pr * w0v.y + Pi * w0v.x;
        if (kh >= 1 && kh <= 6) {
            const float Qr = baser + A - Bv;
            const float Qi = basei + Cv + D;
            const int kh2 = 14 - kh;
            const float2 w1v = wt2c[(kh2 * 8 + kw) * CC];
            // Z[kh2,kw] = conj(Q) * w
            buf[kh2 * 16 + 2 * kw]     = Qr * w1v.x + Qi * w1v.y;
            buf[kh2 * 16 + 2 * kw + 1] = Qr * w1v.y - Qi * w1v.x;
        }
    }
}

__global__ __launch_bounds__(NTH, 3)
void gfilter_kernel(const float* __restrict__ x,
                    const float* __restrict__ wt,
                    float* __restrict__ y)
{
    DEF_TWIDDLES;
    extern __shared__ float sbuf[];

    const int tid  = threadIdx.x;
    const int cl   = tid & (CB - 1);
    const int role = tid >> 6;            // 0..3, uniform per warp
    const int b    = blockIdx.y;
    const int c    = blockIdx.x * CB + cl;

    float* buf = sbuf + cl * STR;
    const int base = (b * 196) * CC + c;
    const float* xb = x + base;

    // ---- Pass 1: real DFT over H (h-pair folded) -> G[kh=0..7][w] ----------
    #pragma unroll
    for (int i = 0; i < 4; ++i) {
        const int w0 = role + 4 * i;
        if (w0 < 14) {
            float xv[14];
            #pragma unroll
            for (int h = 0; h < 14; ++h)
                xv[h] = xb[(h * 14 + w0) * CC];
            float e[6], o[6];
            #pragma unroll
            for (int j = 1; j <= 6; ++j) {
                e[j-1] = xv[j] + xv[14 - j];
                o[j-1] = xv[j] - xv[14 - j];
            }
            #pragma unroll
            for (int kh = 0; kh < 8; ++kh) {
                float gr = (kh & 1) ? (xv[0] - xv[7]) : (xv[0] + xv[7]);
                float gi = 0.f;
                #pragma unroll
                for (int j = 1; j <= 6; ++j) {
                    const int m = (kh * j) % 14;
                    gr = fmaf(e[j-1],  COS14[m], gr);
                    gi = fmaf(o[j-1], -SIN14[m], gi);
                }
                buf[kh * 28 + 2 * w0]     = gr;
                buf[kh * 28 + 2 * w0 + 1] = gi;
            }
        }
    }
    __syncthreads();

    // ---- Pass 2: DFT over W (w-pair folded, P/Q shared) + weight multiply --
    {
        const int kh0 = 2 * role, kh1 = kh0 + 1;
        // Stage + fold both rows into registers BEFORE the sync (in-place
        // overwrite of the G region follows).
        float g0r0, g0i0, g0r7, g0i7, g1r0, g1i0, g1r7, g1i7;
        float er0[6], or0[6], ei0[6], oi0[6];
        float er1[6], or1[6], ei1[6], oi1[6];
        {
            float a, bb;
            g0r0 = buf[kh0 * 28 + 0];  g0i0 = buf[kh0 * 28 + 1];
            g0r7 = buf[kh0 * 28 + 14]; g0i7 = buf[kh0 * 28 + 15];
            g1r0 = buf[kh1 * 28 + 0];  g1i0 = buf[kh1 * 28 + 1];
            g1r7 = buf[kh1 * 28 + 14]; g1i7 = buf[kh1 * 28 + 15];
            #pragma unroll
            for (int j = 1; j <= 6; ++j) {
                a = buf[kh0 * 28 + 2 * j];     bb = buf[kh0 * 28 + 2 * (14 - j)];
                er0[j-1] = a + bb; or0[j-1] = a - bb;
                a = buf[kh0 * 28 + 2 * j + 1]; bb = buf[kh0 * 28 + 2 * (14 - j) + 1];
                ei0[j-1] = a + bb; oi0[j-1] = a - bb;
                a = buf[kh1 * 28 + 2 * j];     bb = buf[kh1 * 28 + 2 * (14 - j)];
                er1[j-1] = a + bb; or1[j-1] = a - bb;
                a = buf[kh1 * 28 + 2 * j + 1]; bb = buf[kh1 * 28 + 2 * (14 - j) + 1];
                ei1[j-1] = a + bb; oi1[j-1] = a - bb;
            }
        }
        __syncthreads();
        const float2* wt2c = reinterpret_cast<const float2*>(wt) + c;
        pass2_row(kh0, g0r0, g0i0, g0r7, g0i7, er0, or0, ei0, oi0, buf, wt2c);
        pass2_row(kh1, g1r0, g1i0, g1r7, g1i7, er1, or1, ei1, oi1, buf, wt2c);
    }
    __syncthreads();

    // ---- Pass 3: inverse DFT over H (r-pair + h-pair folded), per column ---
    #pragma unroll
    for (int jj = 0; jj < 2; ++jj) {
        const int kw = 2 * role + jj;
        float zr[14], zi[14];
        #pragma unroll
        for (int r = 0; r < 14; ++r) {
            zr[r] = buf[r * 16 + 2 * kw];
            zi[r] = buf[r * 16 + 2 * kw + 1];
        }
        float ezr[6], ozr[6], ezi[6], ozi[6];
        #pragma unroll
        for (int j = 1; j <= 6; ++j) {
            ezr[j-1] = zr[j] + zr[14 - j];
            ozr[j-1] = zr[j] - zr[14 - j];
            ezi[j-1] = zi[j] + zi[14 - j];
            ozi[j-1] = zi[j] - zi[14 - j];
        }
        #pragma unroll
        for (int h = 0; h < 8; ++h) {
            float Cr = (h & 1) ? (zr[0] - zr[7]) : (zr[0] + zr[7]);
            float Ci = (h & 1) ? (zi[0] - zi[7]) : (zi[0] + zi[7]);
            float Sr = 0.f, Si = 0.f;
            #pragma unroll
            for (int j = 1; j <= 6; ++j) {
                const int m = (j * h) % 14;
                Cr = fmaf(ezr[j-1], COS14[m], Cr);
                Ci = fmaf(ezi[j-1], COS14[m], Ci);
                Sr = fmaf(ozr[j-1], SIN14[m], Sr);
                Si = fmaf(ozi[j-1], SIN14[m], Si);
            }
            buf[h * 16 + 2 * kw]     = Cr - Si;
            buf[h * 16 + 2 * kw + 1] = Ci + Sr;
            if (h >= 1 && h <= 6) {
                buf[(14 - h) * 16 + 2 * kw]     = Cr + Si;
                buf[(14 - h) * 16 + 2 * kw + 1] = Ci - Sr;
            }
        }
    }
    __syncthreads();

    // ---- Pass 4: c2r over W (w-pair folded) + ortho scale, write out -------
    float* yb = y + base;
    #pragma unroll
    for (int i = 0; i < 4; ++i) {
        const int h = role + 4 * i;
        if (h < 14) {
            float yr[8], yi[8];
            #pragma unroll
            for (int kw = 0; kw < 8; ++kw) {
                yr[kw] = buf[h * 16 + 2 * kw];
                yi[kw] = buf[h * 16 + 2 * kw + 1];
            }
            const float b0 = 0.5f * yr[0], b7 = 0.5f * yr[7];
            #pragma unroll
            for (int w = 0; w < 8; ++w) {
                float Cv = 0.f, Sv = 0.f;
                #pragma unroll
                for (int kw = 1; kw <= 6; ++kw) {
                    const int m = (kw * w) % 14;
                    Cv = fmaf(yr[kw], COS14[m], Cv);
                    Sv = fmaf(yi[kw], SIN14[m], Sv);
                }
                const float bse = (w & 1) ? (b0 - b7) : (b0 + b7);
                yb[(h * 14 + w) * CC] = (bse + Cv - Sv) * (1.0f / 98.0f);
                if (w >= 1 && w <= 6)
                    yb[(h * 14 + 14 - w) * CC] = (bse + Cv + Sv) * (1.0f / 98.0f);
            }
        }
    }
}

extern "C" void kernel_launch(void* const* d_in, const int* in_sizes, int n_in,
                              void* d_out, int out_size)
{
    (void)in_sizes; (void)n_in; (void)out_size;
    const float* x  = (const float*)d_in[0];
    const float* wt = (const float*)d_in[1];
    float* y        = (float*)d_out;

    const int smem_bytes = CB * STR * (int)sizeof(float); // 58624
    cudaFuncSetAttribute(gfilter_kernel,
                         cudaFuncAttributeMaxDynamicSharedMemorySize, smem_bytes);

    dim3 grid(CC / CB, 128); // (12, 128)
    gfilter_kernel<<<grid, NTH, smem_bytes>>>(x, wt, y);
}

// round 4
// speedup vs baseline: 4.6328x; 1.1910x over previous
#include <cuda_runtime.h>

// GlobalFilter: y = irfft2(rfft2(x, ortho) * W, ortho)
// x: [128,14,14,768] f32, W: [14,8,768,2] f32.
// R4: packed f32x2 math (FFMA2), 64-bit [elem][channel] smem layout,
//     CB=32 / 8 roles / 4 CTAs per SM.

#define CC  768
#define CB  32
#define NTH 256

typedef unsigned long long ull;

__device__ __forceinline__ ull pk(float lo, float hi) {
    ull r; asm("mov.b64 %0, {%1,%2};" : "=l"(r) : "f"(lo), "f"(hi)); return r;
}
__device__ __forceinline__ void upk(ull v, float& lo, float& hi) {
    asm("mov.b64 {%0,%1}, %2;" : "=f"(lo), "=f"(hi) : "l"(v));
}
__device__ __forceinline__ ull f2fma(ull a, ull b, ull c) {
    ull d; asm("fma.rn.f32x2 %0, %1, %2, %3;" : "=l"(d) : "l"(a), "l"(b), "l"(c)); return d;
}
__device__ __forceinline__ ull f2add(ull a, ull b) {
    ull d; asm("add.rn.f32x2 %0, %1, %2;" : "=l"(d) : "l"(a), "l"(b)); return d;
}
__device__ __forceinline__ ull f2sub(ull a, ull b) {
    ull d; asm("sub.rn.f32x2 %0, %1, %2;" : "=l"(d) : "l"(a), "l"(b)); return d;
}
// compile-time packed constant
__host__ __device__ constexpr ull pkc(float lo, float hi) {
    return (ull)__builtin_bit_cast(unsigned int, lo)
         | ((ull)__builtin_bit_cast(unsigned int, hi) << 32);
}

#define DEF_TWIDDLES \
    constexpr float COS14[14] = { \
         1.0f,                 0.9009688679024191f,  0.6234898018587336f, \
         0.22252093395631445f,-0.22252093395631445f,-0.6234898018587336f, \
        -0.9009688679024191f, -1.0f,                -0.9009688679024191f, \
        -0.6234898018587336f, -0.22252093395631445f, 0.22252093395631445f, \
         0.6234898018587336f,  0.9009688679024191f }; \
    constexpr float SIN14[14] = { \
         0.0f,                 0.43388373911755823f, 0.7818314824680298f, \
         0.9749279121818236f,  0.9749279121818236f,  0.7818314824680298f, \
         0.43388373911755823f, 0.0f,                -0.43388373911755823f, \
        -0.7818314824680298f, -0.9749279121818236f, -0.9749279121818236f, \
        -0.7818314824680298f, -0.43388373911755823f }

__global__ __launch_bounds__(NTH, 4)
void gfilter_kernel(const float* __restrict__ x,
                    const float* __restrict__ wt,
                    float* __restrict__ y)
{
    DEF_TWIDDLES;
    extern __shared__ ull sbuf[];   // 112 slots x 32 channels, 8B each

    const int tid  = threadIdx.x;
    const int cl   = tid & 31;
    const int role = tid >> 5;      // 0..7, one warp per role
    const int b    = blockIdx.y;
    const int c    = blockIdx.x * CB + cl;

    ull* bufc = sbuf + cl;          // index: slot*32
    const int base = (b * 196) * CC + c;
    const float* xb = x + base;

    // ---- Pass 1: real DFT over H (h-folded, packed gr/gi) ------------------
    // G slot layout: (kh*14 + w), kh = 0..7
    #pragma unroll
    for (int i = 0; i < 2; ++i) {
        const int w0 = role + 8 * i;
        if (i == 0 || role < 6) {
            float xv[14];
            #pragma unroll
            for (int h = 0; h < 14; ++h)
                xv[h] = xb[(h * 14 + w0) * CC];
            ull eo[7];
            #pragma unroll
            for (int j = 1; j <= 6; ++j)
                eo[j] = pk(xv[j] + xv[14 - j], xv[j] - xv[14 - j]);
            const float be = xv[0] + xv[7], bo = xv[0] - xv[7];
            #pragma unroll
            for (int kh = 0; kh < 8; ++kh) {
                ull acc = pk((kh & 1) ? bo : be, 0.f);
                #pragma unroll
                for (int j = 1; j <= 6; ++j) {
                    constexpr int NN = 14;
                    const int m = (kh * j) % NN;
                    acc = f2fma(eo[j], pkc(COS14[m], -SIN14[m]), acc);
                }
                bufc[(kh * 14 + w0) * 32] = acc;
            }
        }
    }
    __syncthreads();

    // ---- Pass 2: DFT over W (w-folded, P/Q shared) + weight multiply -------
    // reads G row kh = role; writes Z rows kh and 14-kh at slots (kh*8 + kw)
    {
        const int kh = role;
        ull g[14];
        #pragma unroll
        for (int w = 0; w < 14; ++w)
            g[w] = bufc[(kh * 14 + w) * 32];
        ull E[7], O[7];
        #pragma unroll
        for (int j = 1; j <= 6; ++j) {
            E[j] = f2add(g[j], g[14 - j]);   // (er, ei)
            O[j] = f2sub(g[j], g[14 - j]);   // (or, oi)
        }
        const ull basep = f2add(g[0], g[7]);
        const ull basem = f2sub(g[0], g[7]);
        __syncthreads();                      // all G rows staged before Z overwrite

        const float2* wt2c = reinterpret_cast<const float2*>(wt) + c;
        #pragma unroll
        for (int kw = 0; kw < 8; ++kw) {
            ull AC = 0ull, DB = 0ull;         // (A, C), (D, B)
            #pragma unroll
            for (int j = 1; j <= 6; ++j) {
                const int m = (kw * j) % 14;
                AC = f2fma(E[j], pkc(COS14[m], COS14[m]), AC);
                if ((m % 7) != 0)             // sin == 0 -> skip
                    DB = f2fma(O[j], pkc(SIN14[m], SIN14[m]), DB);
            }
            float A, Cv, D, Bv, br, bi;
            upk(AC, A, Cv); upk(DB, D, Bv);
            upk((kw & 1) ? basem : basep, br, bi);
            const float Pr = br + A + Bv;
            const float Pi = bi + Cv - D;
            const float2 w0v = wt2c[(kh * 8 + kw) * CC];
            bufc[(kh * 8 + kw) * 32] =
                pk(fmaf(-Pi, w0v.y, Pr * w0v.x), fmaf(Pi, w0v.x, Pr * w0v.y));
            if (kh >= 1 && kh <= 6) {
                const float Qr = br + A - Bv;
                const float Qi = bi + Cv + D;
                const float2 w1v = wt2c[((14 - kh) * 8 + kw) * CC];
                // conj(Q) * w
                bufc[((14 - kh) * 8 + kw) * 32] =
                    pk(fmaf(Qi, w1v.y, Qr * w1v.x), fmaf(-Qi, w1v.x, Qr * w1v.y));
            }
        }
    }
    __syncthreads();

    // ---- Pass 3: inverse DFT over H (r-folded + h-paired), column kw=role --
    {
        const int kw = role;
        ull z[14];
        #pragma unroll
        for (int r = 0; r < 14; ++r)
            z[r] = bufc[(r * 8 + kw) * 32];
        ull EZ[7], OZ[7];
        #pragma unroll
        for (int j = 1; j <= 6; ++j) {
            EZ[j] = f2add(z[j], z[14 - j]);
            OZ[j] = f2sub(z[j], z[14 - j]);
        }
        const ull basep = f2add(z[0], z[7]);
        const ull basem = f2sub(z[0], z[7]);
        #pragma unroll
        for (int h = 0; h < 8; ++h) {
            ull Cacc = (h & 1) ? basem : basep;   // (Cr, Ci)
            ull Sacc = 0ull;                      // (Sr, Si)
            #pragma unroll
            for (int j = 1; j <= 6; ++j) {
                const int m = (j * h) % 14;
                Cacc = f2fma(EZ[j], pkc(COS14[m], COS14[m]), Cacc);
                if ((m % 7) != 0)
                    Sacc = f2fma(OZ[j], pkc(SIN14[m], SIN14[m]), Sacc);
            }
            float sr, si; upk(Sacc, sr, si);
            bufc[(h * 8 + kw) * 32] = f2add(Cacc, pk(-si, sr));
            if (h >= 1 && h <= 6)
                bufc[((14 - h) * 8 + kw) * 32] = f2add(Cacc, pk(si, -sr));
        }
    }
    __syncthreads();

    // ---- Pass 4: c2r over W (w-paired) + ortho scale, write out ------------
    float* yb = y + base;
    #pragma unroll
    for (int i = 0; i < 2; ++i) {
        const int h = role + 8 * i;
        if (i == 0 || role < 6) {
            ull yv[8];
            #pragma unroll
            for (int kw = 0; kw < 8; ++kw)
                yv[kw] = bufc[(h * 8 + kw) * 32];
            float yr0, yi0, yr7, yi7;
            upk(yv[0], yr0, yi0); upk(yv[7], yr7, yi7);
            const float b0 = 0.5f * yr0, b7 = 0.5f * yr7;
            #pragma unroll
            for (int w = 0; w < 8; ++w) {
                ull acc = 0ull;                   // (Cv, Sv)
                #pragma unroll
                for (int kw = 1; kw <= 6; ++kw) {
                    const int m = (kw * w) % 14;
                    acc = f2fma(yv[kw], pkc(COS14[m], SIN14[m]), acc);
                }
                float Cv, Sv; upk(acc, Cv, Sv);
                const float bse = (w & 1) ? (b0 - b7) : (b0 + b7);
                yb[(h * 14 + w) * CC] = (bse + Cv - Sv) * (1.0f / 98.0f);
                if (w >= 1 && w <= 6)
                    yb[(h * 14 + 14 - w) * CC] = (bse + Cv + Sv) * (1.0f / 98.0f);
            }
        }
    }
}

extern "C" void kernel_launch(void* const* d_in, const int* in_sizes, int n_in,
                              void* d_out, int out_size)
{
    (void)in_sizes; (void)n_in; (void)out_size;
    const float* x  = (const float*)d_in[0];
    const float* wt = (const float*)d_in[1];
    float* y        = (float*)d_out;

    const int smem_bytes = 112 * CB * (int)sizeof(ull); // 28672
    dim3 grid(CC / CB, 128); // (24, 128)
    gfilter_kernel<<<grid, NTH, smem_bytes>>>(x, wt, y);
}

// round 5
// speedup vs baseline: 5.3889x; 1.1632x over previous
#include <cuda_runtime.h>

// GlobalFilter: y = irfft2(rfft2(x, ortho) * W, ortho)
// x: [128,14,14,768] f32, W: [14,8,768,2] f32.
// R5: W-first 3-pass pipeline. Pass B fuses fwd-H + weight + inv-H in
//     registers -> only 2 smem transposes. Packed f32x2 (FFMA2) throughout.

#define CC  768
#define CB  32
#define NTH 256

typedef unsigned long long ull;

__device__ __forceinline__ ull pk(float lo, float hi) {
    ull r; asm("mov.b64 %0, {%1,%2};" : "=l"(r) : "f"(lo), "f"(hi)); return r;
}
__device__ __forceinline__ void upk(ull v, float& lo, float& hi) {
    asm("mov.b64 {%0,%1}, %2;" : "=f"(lo), "=f"(hi) : "l"(v));
}
__device__ __forceinline__ ull f2fma(ull a, ull b, ull c) {
    ull d; asm("fma.rn.f32x2 %0, %1, %2, %3;" : "=l"(d) : "l"(a), "l"(b), "l"(c)); return d;
}
__device__ __forceinline__ ull f2add(ull a, ull b) {
    ull d; asm("add.rn.f32x2 %0, %1, %2;" : "=l"(d) : "l"(a), "l"(b)); return d;
}
__device__ __forceinline__ ull f2sub(ull a, ull b) {
    ull d; asm("sub.rn.f32x2 %0, %1, %2;" : "=l"(d) : "l"(a), "l"(b)); return d;
}
__host__ __device__ constexpr ull pkc(float lo, float hi) {
    return (ull)__builtin_bit_cast(unsigned int, lo)
         | ((ull)__builtin_bit_cast(unsigned int, hi) << 32);
}
// complex multiply (packed X) by float2 weight
__device__ __forceinline__ ull cmulw(ull X, float2 w) {
    float xr, xi; upk(X, xr, xi);
    return pk(fmaf(-xi, w.y, xr * w.x), fmaf(xi, w.x, xr * w.y));
}

#define DEF_TWIDDLES \
    constexpr float COS14[14] = { \
         1.0f,                 0.9009688679024191f,  0.6234898018587336f, \
         0.22252093395631445f,-0.22252093395631445f,-0.6234898018587336f, \
        -0.9009688679024191f, -1.0f,                -0.9009688679024191f, \
        -0.6234898018587336f, -0.22252093395631445f, 0.22252093395631445f, \
         0.6234898018587336f,  0.9009688679024191f }; \
    constexpr float SIN14[14] = { \
         0.0f,                 0.43388373911755823f, 0.7818314824680298f, \
         0.9749279121818236f,  0.9749279121818236f,  0.7818314824680298f, \
         0.43388373911755823f, 0.0f,                -0.43388373911755823f, \
        -0.7818314824680298f, -0.9749279121818236f, -0.9749279121818236f, \
        -0.7818314824680298f, -0.43388373911755823f }

__global__ __launch_bounds__(NTH, 4)
void gfilter_kernel(const float* __restrict__ x,
                    const float* __restrict__ wt,
                    float* __restrict__ y)
{
    DEF_TWIDDLES;
    extern __shared__ ull sbuf[];   // 112 slots x 32 channels, 8B each

    const int tid  = threadIdx.x;
    const int cl   = tid & 31;
    const int role = tid >> 5;      // 0..7, one warp per role
    const int b    = blockIdx.y;
    const int c    = blockIdx.x * CB + cl;

    ull* bufc = sbuf + cl;          // index: slot*32; slot = h*8 + kw
    const int base = (b * 196) * CC + c;
    const float* xb = x + base;

    // ---- Pass A: rfft over W on rows read straight from global -------------
    #pragma unroll
    for (int i = 0; i < 2; ++i) {
        const int h = role + 8 * i;
        if (i == 0 || role < 6) {
            float xv[14];
            #pragma unroll
            for (int w = 0; w < 14; ++w)
                xv[w] = xb[(h * 14 + w) * CC];
            ull eo[7];
            #pragma unroll
            for (int j = 1; j <= 6; ++j)
                eo[j] = pk(xv[j] + xv[14 - j], xv[j] - xv[14 - j]);
            const float be = xv[0] + xv[7], bo = xv[0] - xv[7];
            #pragma unroll
            for (int kw = 0; kw < 8; ++kw) {
                ull acc = pk((kw & 1) ? bo : be, 0.f);   // (re, im)
                #pragma unroll
                for (int j = 1; j <= 6; ++j) {
                    const int m = (kw * j) % 14;
                    acc = f2fma(eo[j], pkc(COS14[m], -SIN14[m]), acc);
                }
                bufc[(h * 8 + kw) * 32] = acc;
            }
        }
    }
    __syncthreads();

    // ---- Pass B: fwd H-DFT + weight + inv H-DFT, one kw column per warp ----
    {
        const int kw = role;
        ull F[14];
        #pragma unroll
        for (int h = 0; h < 14; ++h)
            F[h] = bufc[(h * 8 + kw) * 32];
        // forward folds over h
        ull E[7], O[7];
        #pragma unroll
        for (int j = 1; j <= 6; ++j) {
            E[j] = f2add(F[j], F[14 - j]);
            O[j] = f2sub(F[j], F[14 - j]);
        }
        const ull fbp = f2add(F[0], F[7]);
        const ull fbm = f2sub(F[0], F[7]);

        const float2* wt2c = reinterpret_cast<const float2*>(wt) + c;

        // forward per kh-pair, weight-multiply, fold for inverse on the fly
        ull X0, X7, EZ[7], OZ[7];
        #pragma unroll
        for (int kh = 0; kh < 8; ++kh) {
            ull Cacc = (kh & 1) ? fbm : fbp;  // (Cr, Ci)
            ull Sacc = 0ull;                  // (Sr, Si)
            #pragma unroll
            for (int j = 1; j <= 6; ++j) {
                const int m = (kh * j) % 14;
                Cacc = f2fma(E[j], pkc(COS14[m], COS14[m]), Cacc);
                if ((m % 7) != 0)
                    Sacc = f2fma(O[j], pkc(SIN14[m], SIN14[m]), Sacc);
            }
            float sr, si; upk(Sacc, sr, si);
            // X[kh] = C - iS ; X[14-kh] = C + iS
            ull Xa = f2add(Cacc, pk(si, -sr));
            Xa = cmulw(Xa, wt2c[(kh * 8 + kw) * CC]);
            if (kh == 0)      X0 = Xa;
            else if (kh == 7) X7 = Xa;
            else {
                ull Xb = f2add(Cacc, pk(-si, sr));
                Xb = cmulw(Xb, wt2c[((14 - kh) * 8 + kw) * CC]);
                EZ[kh] = f2add(Xa, Xb);
                OZ[kh] = f2sub(Xa, Xb);
            }
        }
        // inverse H-DFT (e^{+i}), h paired with 14-h; write back to same column
        const ull ibp = f2add(X0, X7);
        const ull ibm = f2sub(X0, X7);
        #pragma unroll
        for (int h = 0; h < 8; ++h) {
            ull Cacc = (h & 1) ? ibm : ibp;
            ull Sacc = 0ull;
            #pragma unroll
            for (int j = 1; j <= 6; ++j) {
                const int m = (j * h) % 14;
                Cacc = f2fma(EZ[j], pkc(COS14[m], COS14[m]), Cacc);
                if ((m % 7) != 0)
                    Sacc = f2fma(OZ[j], pkc(SIN14[m], SIN14[m]), Sacc);
            }
            float sr, si; upk(Sacc, sr, si);
            bufc[(h * 8 + kw) * 32] = f2add(Cacc, pk(-si, sr));
            if (h >= 1 && h <= 6)
                bufc[((14 - h) * 8 + kw) * 32] = f2add(Cacc, pk(si, -sr));
        }
    }
    __syncthreads();

    // ---- Pass C: c2r over W (w-paired) + ortho scale, write out ------------
    float* yb = y + base;
    #pragma unroll
    for (int i = 0; i < 2; ++i) {
        const int h = role + 8 * i;
        if (i == 0 || role < 6) {
            ull yv[8];
            #pragma unroll
            for (int kw = 0; kw < 8; ++kw)
                yv[kw] = bufc[(h * 8 + kw) * 32];
            float yr0, yi0, yr7, yi7;
            upk(yv[0], yr0, yi0); upk(yv[7], yr7, yi7);
            const float b0 = 0.5f * yr0, b7 = 0.5f * yr7;
            #pragma unroll
            for (int w = 0; w < 8; ++w) {
                ull acc = 0ull;                   // (Cv, Sv)
                #pragma unroll
                for (int kw = 1; kw <= 6; ++kw) {
                    const int m = (kw * w) % 14;
                    acc = f2fma(yv[kw], pkc(COS14[m], SIN14[m]), acc);
                }
                float Cv, Sv; upk(acc, Cv, Sv);
                const float bse = (w & 1) ? (b0 - b7) : (b0 + b7);
                yb[(h * 14 + w) * CC] = (bse + Cv - Sv) * (1.0f / 98.0f);
                if (w >= 1 && w <= 6)
                    yb[(h * 14 + 14 - w) * CC] = (bse + Cv + Sv) * (1.0f / 98.0f);
            }
        }
    }
}

extern "C" void kernel_launch(void* const* d_in, const int* in_sizes, int n_in,
                              void* d_out, int out_size)
{
    (void)in_sizes; (void)n_in; (void)out_size;
    const float* x  = (const float*)d_in[0];
    const float* wt = (const float*)d_in[1];
    float* y        = (float*)d_out;

    const int smem_bytes = 112 * CB * (int)sizeof(ull); // 28672
    dim3 grid(CC / CB, 128); // (24, 128)
    gfilter_kernel<<<grid, NTH, smem_bytes>>>(x, wt, y);
}